// round 6
// baseline (speedup 1.0000x reference)
#include <cuda_runtime.h>
#include <cstdint>

// diff_lpc2rc: x shape (64, 32768, 16) fp32 -> 2,097,152 independent rows.
// Per row v[0..15]:
//   for i = 1..15:  m = 16 - i; k = v[m];
//     v[t] = (v[t] - k * v[m-1-t]) / (1 - k*k)   for t in [0, m)
//
// R5: 2-stage cp.async double-buffer pipeline (8 tiles/block) so the load of
// tile it+1 overlaps compute+store of tile it. Lane permutation in staging
// makes every smem phase conflict-free with 20-float padded rows.

#define NCOEF 16
#define ROWSTRIDE 20           // 5 16B-chunks per row; 5*r mod 8 distinct for r=0..7
#define TPB 256
#define TILES_PER_BLOCK 8
#define TILE_FLOATS (TPB * NCOEF)
#define BUF_FLOATS (TPB * ROWSTRIDE)

__device__ __forceinline__ float fast_rcp(float x) {
    float r;
    asm("rcp.approx.ftz.f32 %0, %1;" : "=f"(r) : "f"(x));
    return r;
}

__device__ __forceinline__ void lpc2rc_row(float v[NCOEF]) {
    #pragma unroll
    for (int i = 1; i < NCOEF; ++i) {
        const int m = NCOEF - i;
        const float k  = v[m];
        const float nk = -k;
        const float inv = fast_rcp(fmaf(nk, k, 1.0f));   // 1/(1 - k^2)
        #pragma unroll
        for (int t = 0; t < m / 2; ++t) {
            const float a = v[t];
            const float b = v[m - 1 - t];
            v[t]         = fmaf(nk, b, a) * inv;
            v[m - 1 - t] = fmaf(nk, a, b) * inv;
        }
        if (m & 1) {
            const int t = m / 2;
            const float a = v[t];
            v[t] = fmaf(nk, a, a) * inv;
        }
    }
}

// Permuted staging index: lane l of a warp handles float4 (warp window) offset
// foff(l). Row-quads r and r+4 share a phase-octet -> smem 16B-chunks
// {5r+c} U {5(r+4)+c} cover all 8 banks-groups exactly once per phase.
__device__ __forceinline__ int stage_foff(int lane) {
    const int o  = lane >> 3;         // 0..3
    const int w2 = (lane >> 2) & 1;   // 0..1
    const int c  = lane & 3;          // 0..3
    return (o + 4 * w2) * 4 + c;      // row' in 0..7, col c
}

__global__ __launch_bounds__(TPB) void diff_lpc2rc_kernel(
    const float* __restrict__ x, float* __restrict__ out, int ntiles)
{
    __shared__ float s[2 * BUF_FLOATS];
    const int t    = threadIdx.x;
    const int warp = t >> 5;
    const int lane = t & 31;
    const int foff = stage_foff(lane);          // per-warp float4 offset (0..31)
    const int tile0 = blockIdx.x * TILES_PER_BLOCK;

    const uint32_t sbase = (uint32_t)__cvta_generic_to_shared(s);

    // ---- prologue: prefetch tile 0 into buf 0 ----
    {
        const float4* in4 = reinterpret_cast<const float4*>(x) + (size_t)tile0 * TPB * 4;
        #pragma unroll
        for (int kk = 0; kk < 4; ++kk) {
            const int f   = kk * TPB + warp * 32 + foff;   // global float4 idx in tile
            const int row = f >> 2;
            const int c   = f & 3;
            const uint32_t daddr = sbase + (uint32_t)((row * ROWSTRIDE + c * 4) * 4);
            asm volatile("cp.async.cg.shared.global [%0], [%1], 16;\n"
                         :: "r"(daddr), "l"(in4 + f));
        }
        asm volatile("cp.async.commit_group;\n");
    }

    #pragma unroll 1
    for (int it = 0; it < TILES_PER_BLOCK; ++it) {
        const int tile = tile0 + it;
        if (tile >= ntiles) break;
        const int buf = it & 1;
        float* sc = s + buf * BUF_FLOATS;
        const uint32_t scb = sbase + (uint32_t)(buf * BUF_FLOATS * 4);
        (void)scb;

        // wait for tile it's data; barrier also guarantees everyone finished
        // reading the OTHER buffer (tile it-1 store phase) before we refill it.
        asm volatile("cp.async.wait_group 0;\n");
        __syncthreads();

        // prefetch tile it+1 into the other buffer (overlaps compute+store)
        if (it + 1 < TILES_PER_BLOCK && tile + 1 < ntiles) {
            const uint32_t obase = sbase + (uint32_t)((buf ^ 1) * BUF_FLOATS * 4);
            const float4* in4 = reinterpret_cast<const float4*>(x) + (size_t)(tile + 1) * TPB * 4;
            #pragma unroll
            for (int kk = 0; kk < 4; ++kk) {
                const int f   = kk * TPB + warp * 32 + foff;
                const int row = f >> 2;
                const int c   = f & 3;
                const uint32_t daddr = obase + (uint32_t)((row * ROWSTRIDE + c * 4) * 4);
                asm volatile("cp.async.cg.shared.global [%0], [%1], 16;\n"
                             :: "r"(daddr), "l"(in4 + f));
            }
            asm volatile("cp.async.commit_group;\n");
        } else {
            // keep group count consistent for wait_group 0 semantics (no-op group)
            asm volatile("cp.async.commit_group;\n");
        }

        // ---- compute: one row per thread, conflict-free LDS.128 (stride 20) ----
        float v[NCOEF];
        {
            const float4 a0 = *reinterpret_cast<const float4*>(&sc[t * ROWSTRIDE + 0]);
            const float4 a1 = *reinterpret_cast<const float4*>(&sc[t * ROWSTRIDE + 4]);
            const float4 a2 = *reinterpret_cast<const float4*>(&sc[t * ROWSTRIDE + 8]);
            const float4 a3 = *reinterpret_cast<const float4*>(&sc[t * ROWSTRIDE + 12]);
            v[0]=a0.x; v[1]=a0.y; v[2]=a0.z; v[3]=a0.w;
            v[4]=a1.x; v[5]=a1.y; v[6]=a1.z; v[7]=a1.w;
            v[8]=a2.x; v[9]=a2.y; v[10]=a2.z; v[11]=a2.w;
            v[12]=a3.x; v[13]=a3.y; v[14]=a3.z; v[15]=a3.w;
        }

        lpc2rc_row(v);

        *reinterpret_cast<float4*>(&sc[t * ROWSTRIDE + 0])  = make_float4(v[0],  v[1],  v[2],  v[3]);
        *reinterpret_cast<float4*>(&sc[t * ROWSTRIDE + 4])  = make_float4(v[4],  v[5],  v[6],  v[7]);
        *reinterpret_cast<float4*>(&sc[t * ROWSTRIDE + 8])  = make_float4(v[8],  v[9],  v[10], v[11]);
        *reinterpret_cast<float4*>(&sc[t * ROWSTRIDE + 12]) = make_float4(v[12], v[13], v[14], v[15]);
        __syncthreads();

        // ---- stage out: conflict-free LDS.128 gather, coalesced STG.128 ----
        float4* out4 = reinterpret_cast<float4*>(out) + (size_t)tile * TPB * 4;
        #pragma unroll
        for (int kk = 0; kk < 4; ++kk) {
            const int f   = kk * TPB + warp * 32 + foff;
            const int row = f >> 2;
            const int c   = f & 3;
            out4[f] = *reinterpret_cast<const float4*>(&sc[row * ROWSTRIDE + c * 4]);
        }
    }
}

extern "C" void kernel_launch(void* const* d_in, const int* in_sizes, int n_in,
                              void* d_out, int out_size)
{
    const float* x = (const float*)d_in[0];
    float* out = (float*)d_out;
    const int nrows  = in_sizes[0] / NCOEF;               // 2,097,152
    const int ntiles = (nrows + TPB - 1) / TPB;           // 8192
    const int blocks = (ntiles + TILES_PER_BLOCK - 1) / TILES_PER_BLOCK;  // 1024
    diff_lpc2rc_kernel<<<blocks, TPB>>>(x, out, ntiles);
}